// round 3
// baseline (speedup 1.0000x reference)
#include <cuda_runtime.h>
#include <math.h>

// SE block: B=32, H=W=56 (HW=3136), C=256, R=16.
// inputs [B,HW,C] fp32 (NHWC, channel-contiguous), W1 [C,16], b1[16], W2 [16,C], b2[C].
// out = inputs * sigmoid(relu(mean_hw(inputs) @ W1 + b1) @ W2 + b2), broadcast over HW.

#define Bb      32
#define HW      3136
#define Cc      256
#define CR      16
#define KSPLIT  32          // spatial chunks per batch for the pool pass
#define CHUNK   98          // 3136 / 32
#define CQ      64          // C/4 float4 quads per position

// Scratch (no device allocation allowed): partial sums + excitation vector.
__device__ float g_partial[Bb * KSPLIT * Cc];   // 1 MB
__device__ float g_exc[Bb * Cc];                // 32 KB

// ---------------------------------------------------------------------------
// Pass 1: partial spatial sums. grid = B*KSPLIT blocks, 256 threads.
// Thread layout: q = tid&63 -> channel quad (float4), pg = tid>>6 -> one of 4
// position sub-streams. Loads are fully coalesced (256 threads read 4 KB of
// 4 consecutive spatial rows per iteration).
// ---------------------------------------------------------------------------
__global__ void __launch_bounds__(256) se_pool_partial(const float* __restrict__ in)
{
    const int b   = blockIdx.x / KSPLIT;
    const int k   = blockIdx.x % KSPLIT;
    const int tid = threadIdx.x;
    const int q   = tid & 63;
    const int pg  = tid >> 6;

    const float4* __restrict__ in4 = reinterpret_cast<const float4*>(in)
                                     + (size_t)b * HW * CQ;

    float4 acc = make_float4(0.f, 0.f, 0.f, 0.f);
    const int pEnd = (k + 1) * CHUNK;
    for (int p = k * CHUNK + pg; p < pEnd; p += 4) {
        float4 v = __ldg(&in4[(size_t)p * CQ + q]);
        acc.x += v.x; acc.y += v.y; acc.z += v.z; acc.w += v.w;
    }

    __shared__ float4 s[256];
    s[tid] = acc;
    __syncthreads();

    if (tid < 64) {
        float4 a = s[tid];
        float4 c = s[tid + 64];
        float4 d = s[tid + 128];
        float4 e = s[tid + 192];
        float4 r = make_float4(a.x + c.x + d.x + e.x,
                               a.y + c.y + d.y + e.y,
                               a.z + c.z + d.z + e.z,
                               a.w + c.w + d.w + e.w);
        reinterpret_cast<float4*>(g_partial)[(b * KSPLIT + k) * CQ + tid] = r;
    }
}

// ---------------------------------------------------------------------------
// Pass 2: finish mean, tiny MLP (256 -> 16 relu -> 256 sigmoid).
// grid = B blocks, 256 threads. Negligible cost (~2 us total).
// ---------------------------------------------------------------------------
__global__ void __launch_bounds__(256) se_excite(const float* __restrict__ W1,
                                                 const float* __restrict__ b1,
                                                 const float* __restrict__ W2,
                                                 const float* __restrict__ b2)
{
    const int b = blockIdx.x;
    const int c = threadIdx.x;

    __shared__ float sq[Cc];
    __shared__ float hs[CR];

    // reduce KSPLIT partials -> mean
    float sum = 0.f;
    #pragma unroll
    for (int k = 0; k < KSPLIT; k++)
        sum += g_partial[(b * KSPLIT + k) * Cc + c];
    sq[c] = sum * (1.0f / (float)HW);
    __syncthreads();

    // h = relu(sq @ W1 + b1)   (16 outputs; threads 0..15)
    if (c < CR) {
        float h = b1[c];
        #pragma unroll 8
        for (int i = 0; i < Cc; i++)
            h = fmaf(sq[i], W1[i * CR + c], h);
        hs[c] = fmaxf(h, 0.f);
    }
    __syncthreads();

    // e = sigmoid(h @ W2 + b2)  (256 outputs; one per thread)
    float e = b2[c];
    #pragma unroll
    for (int j = 0; j < CR; j++)
        e = fmaf(hs[j], W2[j * Cc + c], e);
    g_exc[b * Cc + c] = 1.0f / (1.0f + __expf(-e));
}

// ---------------------------------------------------------------------------
// Pass 3: out = in * exc[b,c], float4 grid-stride. Excitation (8 KB) lives in
// L1/L2; main cost is the streaming read+write of 2 x 102.8 MB.
// ---------------------------------------------------------------------------
__global__ void __launch_bounds__(256) se_scale(const float* __restrict__ in,
                                                float* __restrict__ out)
{
    const float4* __restrict__ in4  = reinterpret_cast<const float4*>(in);
    float4* __restrict__       out4 = reinterpret_cast<float4*>(out);
    const float4* __restrict__ exc4 = reinterpret_cast<const float4*>(g_exc);

    const long long total  = (long long)Bb * HW * CQ;      // 6,422,528 float4
    const long long stride = (long long)gridDim.x * blockDim.x;

    for (long long i = (long long)blockIdx.x * blockDim.x + threadIdx.x;
         i < total; i += stride) {
        const int b = (int)(i / (HW * CQ));    // constant divisor -> mul/shift
        const int q = (int)(i & (CQ - 1));
        float4 e = __ldg(&exc4[b * CQ + q]);
        float4 v = in4[i];
        v.x *= e.x; v.y *= e.y; v.z *= e.z; v.w *= e.w;
        out4[i] = v;
    }
}

// ---------------------------------------------------------------------------
extern "C" void kernel_launch(void* const* d_in, const int* in_sizes, int n_in,
                              void* d_out, int out_size)
{
    const float* in = (const float*)d_in[0];
    const float* W1 = (const float*)d_in[1];
    const float* b1 = (const float*)d_in[2];
    const float* W2 = (const float*)d_in[3];
    const float* b2 = (const float*)d_in[4];
    float* out = (float*)d_out;

    se_pool_partial<<<Bb * KSPLIT, 256>>>(in);
    se_excite<<<Bb, 256>>>(W1, b1, W2, b2);
    se_scale<<<2368, 256>>>(in, out);   // 16 waves of 148 SMs
}